// round 6
// baseline (speedup 1.0000x reference)
#include <cuda_runtime.h>
#include <cuda_bf16.h>
#include <cuda_fp16.h>

#define NN 100000
#define EE 1600000
#define DIM 128
#define NH 4
#define HD 32

#define SCAN_B 512
#define SCAN_NB ((NN + SCAN_B - 1) / SCAN_B)   // 196
#define CAP 96                                  // per-warp cached edges in k_agg

// ---------------- device scratch (static — no allocation allowed) ----------------
__device__ uint2 g_hh[(size_t)NN * 32];      // projected features, fp16 [N,128]
__device__ float g_esrc[NN * NH];            // per-node src logits [N,4]
__device__ float g_edst[NN * NH];            // per-node dst logits [N,4]
__device__ int   g_deg[NN];
__device__ int   g_cur[NN];
__device__ int   g_off[NN + 1];
__device__ unsigned long long g_tile[SCAN_NB];  // lookback scan states (hi=state,lo=value)
__device__ int   g_edge_src[EE];             // src ids grouped by dst (CSR)
__device__ int   g_is64;

// ---------------- f32x2 helpers (Blackwell packed fp32 — PTX only) ----------------
__device__ __forceinline__ unsigned long long pk2(float s) {
    unsigned long long d;
    asm("mov.b64 %0, {%1, %1};" : "=l"(d) : "f"(s));
    return d;
}
__device__ __forceinline__ void fma2(unsigned long long& c, unsigned long long a,
                                     unsigned long long b) {
    asm("fma.rn.f32x2 %0, %1, %2, %0;" : "+l"(c) : "l"(a), "l"(b));
}
__device__ __forceinline__ float2 up2(unsigned long long v) {
    float2 r;
    asm("mov.b64 {%0, %1}, %2;" : "=f"(r.x), "=f"(r.y) : "l"(v));
    return r;
}

// ---------------- init + dtype detect (fused) ----------------
__global__ void k_init(const void* src) {
    int i = blockIdx.x * blockDim.x + threadIdx.x;
    if (i < NN) { g_deg[i] = 0; g_cur[i] = 0; }
    if (i < SCAN_NB) g_tile[i] = 0ull;
    if (blockIdx.x == 0 && threadIdx.x < 32) {
        const unsigned* p = (const unsigned*)src;
        int lane = threadIdx.x;
        unsigned hi = p[2 * lane + 1] | p[2 * (lane + 32) + 1];
        unsigned b = __ballot_sync(0xffffffffu, hi == 0u);
        if (lane == 0) g_is64 = (b == 0xffffffffu) ? 1 : 0;
    }
}

// ---------------- GEMM + fused logits ----------------
// h = feat @ fc_w.T  (N x 128 @ 128 x 128), then e_src/e_dst per row.
// block = 256 threads, 64 rows x 128 cols per block. Thread: 4 cols x 8 rows.
// Mainloop uses packed fma.rn.f32x2 (2x fp32 rate on sm_103a).
#define KC 32
__global__ void __launch_bounds__(256) k_gemm(const float* __restrict__ feat,
                                              const float* __restrict__ fc_w,
                                              const float* __restrict__ attn_src,
                                              const float* __restrict__ attn_dst) {
    __shared__ float wT[KC][132];
    __shared__ float fT[KC][68];
    int tid = threadIdx.x;
    int tx = tid & 31;
    int ty = tid >> 5;
    int rbase = blockIdx.x * 64;

    unsigned long long A[16];
#pragma unroll
    for (int r = 0; r < 16; r++) A[r] = 0ull;

    for (int k0 = 0; k0 < DIM; k0 += KC) {
        __syncthreads();
#pragma unroll
        for (int q = 0; q < 4; q++) {
            int id = tid + q * 256;
            int c  = id >> 3;
            int ks = (id & 7) * 4;
            float4 v = *(const float4*)&fc_w[c * DIM + k0 + ks];
            wT[ks + 0][c] = v.x; wT[ks + 1][c] = v.y;
            wT[ks + 2][c] = v.z; wT[ks + 3][c] = v.w;
        }
#pragma unroll
        for (int q = 0; q < 2; q++) {
            int id = tid + q * 256;
            int r  = id >> 3;
            int ks = (id & 7) * 4;
            int gr = rbase + r;
            float4 v = make_float4(0.f, 0.f, 0.f, 0.f);
            if (gr < NN) v = *(const float4*)&feat[(size_t)gr * DIM + k0 + ks];
            fT[ks + 0][r] = v.x; fT[ks + 1][r] = v.y;
            fT[ks + 2][r] = v.z; fT[ks + 3][r] = v.w;
        }
        __syncthreads();
#pragma unroll
        for (int kk = 0; kk < KC; kk++) {
            ulonglong2 w2 = *(const ulonglong2*)&wT[kk][tx * 4];
            float4 fa = *(const float4*)&fT[kk][ty * 8];
            float4 fb = *(const float4*)&fT[kk][ty * 8 + 4];
#define STEP(r, S) { unsigned long long b = pk2(S); \
                     fma2(A[2*(r)], w2.x, b); fma2(A[2*(r)+1], w2.y, b); }
            STEP(0, fa.x) STEP(1, fa.y) STEP(2, fa.z) STEP(3, fa.w)
            STEP(4, fb.x) STEP(5, fb.y) STEP(6, fb.z) STEP(7, fb.w)
#undef STEP
        }
    }

    float4 as4 = *(const float4*)&attn_src[tx * 4];
    float4 ad4 = *(const float4*)&attn_dst[tx * 4];
    int head = tx >> 3;

#pragma unroll
    for (int r = 0; r < 8; r++) {
        int gr = rbase + ty * 8 + r;
        float2 p0 = up2(A[2 * r]);
        float2 p1 = up2(A[2 * r + 1]);
        if (gr < NN) {
            __half2 ha = __floats2half2_rn(p0.x, p0.y);
            __half2 hb = __floats2half2_rn(p1.x, p1.y);
            uint2 u;
            u.x = *(const unsigned*)&ha;
            u.y = *(const unsigned*)&hb;
            g_hh[(size_t)gr * 32 + tx] = u;
        }
        float ps = p0.x * as4.x + p0.y * as4.y + p1.x * as4.z + p1.y * as4.w;
        float pd = p0.x * ad4.x + p0.y * ad4.y + p1.x * ad4.z + p1.y * ad4.w;
#pragma unroll
        for (int o = 1; o < 8; o <<= 1) {
            ps += __shfl_xor_sync(0xffffffffu, ps, o);
            pd += __shfl_xor_sync(0xffffffffu, pd, o);
        }
        if (gr < NN && (tx & 7) == 0) {
            g_esrc[gr * NH + head] = ps;
            g_edst[gr * NH + head] = pd;
        }
    }
}

// ---------------- CSR build ----------------
// histogram, 2 edges per thread (16B vector loads)
__global__ void k_hist(const void* __restrict__ dst) {
    int i = blockIdx.x * blockDim.x + threadIdx.x;   // edge-pair index
    if (2 * i >= EE) return;
    int d0, d1;
    if (g_is64) {
        ulonglong2 v = ((const ulonglong2*)dst)[i];
        d0 = (int)v.x; d1 = (int)v.y;
    } else {
        int2 v = ((const int2*)dst)[i];
        d0 = v.x; d1 = v.y;
    }
    atomicAdd(&g_deg[d0], 1);
    atomicAdd(&g_deg[d1], 1);
}

// single-kernel decoupled-lookback exclusive scan of g_deg -> g_off
__global__ void __launch_bounds__(SCAN_B) k_scan() {
    __shared__ int sm[SCAN_B];
    __shared__ int s_excl;
    int b = blockIdx.x, t = threadIdx.x;
    int i = b * SCAN_B + t;
    int v = (i < NN) ? g_deg[i] : 0;
    sm[t] = v;
    __syncthreads();
#pragma unroll
    for (int off = 1; off < SCAN_B; off <<= 1) {
        int x = (t >= off) ? sm[t - off] : 0;
        __syncthreads();
        sm[t] += x;
        __syncthreads();
    }
    int total = sm[SCAN_B - 1];
    if (t == 0) {
        if (b == 0) {
            atomicExch(&g_tile[0], (2ull << 32) | (unsigned)total);
            s_excl = 0;
        } else {
            atomicExch(&g_tile[b], (1ull << 32) | (unsigned)total);
            int excl = 0;
            int idx = b - 1;
            while (true) {
                unsigned long long e;
                do { e = atomicAdd(&g_tile[idx], 0ull); } while ((e >> 32) == 0ull);
                excl += (int)(unsigned)e;
                if ((e >> 32) == 2ull) break;
                idx--;
            }
            atomicExch(&g_tile[b], (2ull << 32) | (unsigned)(excl + total));
            s_excl = excl;
        }
    }
    __syncthreads();
    int excl = s_excl;
    if (i < NN) g_off[i] = excl + sm[t] - v;          // exclusive
    if (b == SCAN_NB - 1 && t == SCAN_B - 1) g_off[NN] = excl + total;
}

// scatter, 2 edges per thread
__global__ void k_scatter(const void* __restrict__ src, const void* __restrict__ dst) {
    int i = blockIdx.x * blockDim.x + threadIdx.x;   // edge-pair index
    if (2 * i >= EE) return;
    int d0, d1, s0, s1;
    if (g_is64) {
        ulonglong2 vd = ((const ulonglong2*)dst)[i];
        ulonglong2 vs = ((const ulonglong2*)src)[i];
        d0 = (int)vd.x; d1 = (int)vd.y;
        s0 = (int)vs.x; s1 = (int)vs.y;
    } else {
        int2 vd = ((const int2*)dst)[i];
        int2 vs = ((const int2*)src)[i];
        d0 = vd.x; d1 = vd.y;
        s0 = vs.x; s1 = vs.y;
    }
    int p0 = g_off[d0] + atomicAdd(&g_cur[d0], 1);
    g_edge_src[p0] = s0;
    int p1 = g_off[d1] + atomicAdd(&g_cur[d1], 1);
    g_edge_src[p1] = s1;
}

// ---------------- softmax + aggregation: warp per dst node ----------------
__global__ void __launch_bounds__(256) k_agg(const float* __restrict__ feat,
                                             float* __restrict__ out) {
    __shared__ float swt[8][CAP * 4];    // per-warp cached exp-weights [edge][head]
    __shared__ int   ssi[8][CAP];        // per-warp cached src ids
    int wid = threadIdx.x >> 5;
    int n = (blockIdx.x * blockDim.x + threadIdx.x) >> 5;
    int lane = threadIdx.x & 31;
    if (n >= NN) return;
    int beg = g_off[n], end = g_off[n + 1];
    float4 f4 = *(const float4*)&feat[(size_t)n * DIM + lane * 4];
    if (beg == end) {
        *(float4*)&out[(size_t)n * DIM + lane * 4] = f4;
        return;
    }
    float4 ed4 = *(const float4*)&g_edst[n * NH];
    int d = end - beg;
    bool cached = (d <= CAP);

    // phase 1: per-edge exp weights + per-head sums (no max-sub; |e|<~5, safe fp32)
    float4 s4 = make_float4(0.f, 0.f, 0.f, 0.f);
    for (int i = beg + lane; i < end; i += 32) {
        int s = g_edge_src[i];
        float4 es = *(const float4*)&g_esrc[s * NH];
        float ex = es.x + ed4.x; ex = ex > 0.f ? ex : 0.2f * ex;
        float ey = es.y + ed4.y; ey = ey > 0.f ? ey : 0.2f * ey;
        float ez = es.z + ed4.z; ez = ez > 0.f ? ez : 0.2f * ez;
        float ew = es.w + ed4.w; ew = ew > 0.f ? ew : 0.2f * ew;
        float4 w4;
        w4.x = __expf(ex); w4.y = __expf(ey);
        w4.z = __expf(ez); w4.w = __expf(ew);
        if (cached) {
            int j = i - beg;
            ssi[wid][j] = s;
            *(float4*)&swt[wid][j * 4] = w4;
        }
        s4.x += w4.x; s4.y += w4.y; s4.z += w4.z; s4.w += w4.w;
    }
#pragma unroll
    for (int o = 1; o < 32; o <<= 1) {
        s4.x += __shfl_xor_sync(0xffffffffu, s4.x, o);
        s4.y += __shfl_xor_sync(0xffffffffu, s4.y, o);
        s4.z += __shfl_xor_sync(0xffffffffu, s4.z, o);
        s4.w += __shfl_xor_sync(0xffffffffu, s4.w, o);
    }
    __syncwarp();
    int head = lane >> 3;
    float ssum = (head == 0) ? s4.x : (head == 1) ? s4.y : (head == 2) ? s4.z : s4.w;
    float inv = 1.0f / ssum;

    // phase 2: weighted fp16 gather
    float4 acc = make_float4(0.f, 0.f, 0.f, 0.f);
    const uint2* hh = g_hh;
    if (cached) {
        int i = 0;
        for (; i + 2 <= d; i += 2) {
            int s0 = ssi[wid][i];
            int s1 = ssi[wid][i + 1];
            float w0 = swt[wid][i * 4 + head];
            float w1 = swt[wid][(i + 1) * 4 + head];
            uint2 u0 = hh[(size_t)s0 * 32 + lane];
            uint2 u1 = hh[(size_t)s1 * 32 + lane];
            float2 a0 = __half22float2(*(const __half2*)&u0.x);
            float2 b0 = __half22float2(*(const __half2*)&u0.y);
            float2 a1 = __half22float2(*(const __half2*)&u1.x);
            float2 b1 = __half22float2(*(const __half2*)&u1.y);
            acc.x += w0 * a0.x; acc.y += w0 * a0.y;
            acc.z += w0 * b0.x; acc.w += w0 * b0.y;
            acc.x += w1 * a1.x; acc.y += w1 * a1.y;
            acc.z += w1 * b1.x; acc.w += w1 * b1.y;
        }
        for (; i < d; i++) {
            int s = ssi[wid][i];
            float w = swt[wid][i * 4 + head];
            uint2 u = hh[(size_t)s * 32 + lane];
            float2 a = __half22float2(*(const __half2*)&u.x);
            float2 b = __half22float2(*(const __half2*)&u.y);
            acc.x += w * a.x; acc.y += w * a.y;
            acc.z += w * b.x; acc.w += w * b.y;
        }
    } else {
        float edh = (head == 0) ? ed4.x : (head == 1) ? ed4.y : (head == 2) ? ed4.z : ed4.w;
        for (int i = beg; i < end; i++) {
            int s = g_edge_src[i];
            float e = g_esrc[s * NH + head] + edh;
            e = e > 0.f ? e : 0.2f * e;
            float w = __expf(e);
            uint2 u = hh[(size_t)s * 32 + lane];
            float2 a = __half22float2(*(const __half2*)&u.x);
            float2 b = __half22float2(*(const __half2*)&u.y);
            acc.x += w * a.x; acc.y += w * a.y;
            acc.z += w * b.x; acc.w += w * b.y;
        }
    }
    float4 o4;
    o4.x = acc.x * inv + f4.x;
    o4.y = acc.y * inv + f4.y;
    o4.z = acc.z * inv + f4.z;
    o4.w = acc.w * inv + f4.w;
    *(float4*)&out[(size_t)n * DIM + lane * 4] = o4;
}

// ---------------- launch ----------------
extern "C" void kernel_launch(void* const* d_in, const int* in_sizes, int n_in,
                              void* d_out, int out_size) {
    const float* feat     = (const float*)d_in[0];
    const float* fc_w     = (const float*)d_in[1];
    const float* attn_src = (const float*)d_in[2];
    const float* attn_dst = (const float*)d_in[3];
    const void*  src      = d_in[4];
    const void*  dst      = d_in[5];
    float* out = (float*)d_out;

    static cudaStream_t s2 = nullptr;
    static cudaEvent_t evA = nullptr, evB = nullptr;
    if (!s2) {
        cudaStreamCreate(&s2);
        cudaEventCreateWithFlags(&evA, cudaEventDisableTiming);
        cudaEventCreateWithFlags(&evB, cudaEventDisableTiming);
    }

    // fork: CSR build chain on s2 (depends only on src/dst), GEMM on main stream
    cudaEventRecord(evA, 0);
    cudaStreamWaitEvent(s2, evA, 0);

    k_init<<<(NN + 255) / 256, 256, 0, s2>>>(src);
    k_hist<<<(EE / 2 + 255) / 256, 256, 0, s2>>>(dst);
    k_scan<<<SCAN_NB, SCAN_B, 0, s2>>>();
    k_scatter<<<(EE / 2 + 255) / 256, 256, 0, s2>>>(src, dst);
    cudaEventRecord(evB, s2);

    k_gemm<<<(NN + 63) / 64, 256>>>(feat, fc_w, attn_src, attn_dst);

    // join, then aggregate
    cudaStreamWaitEvent(0, evB, 0);
    k_agg<<<(NN + 7) / 8, 256>>>(feat, out);
}

// round 7
// speedup vs baseline: 1.5108x; 1.5108x over previous
#include <cuda_runtime.h>
#include <cuda_bf16.h>
#include <cuda_fp16.h>

#define NN 100000
#define EE 1600000
#define DIM 128
#define NH 4
#define HD 32

#define SCAN_B 512
#define SCAN_NB ((NN + SCAN_B - 1) / SCAN_B)   // 196

// ---------------- device scratch (static — no allocation allowed) ----------------
__device__ uint2 g_hh[(size_t)NN * 32];      // projected features, fp16 [N,128]
__device__ float g_esrc[NN * NH];            // per-node src logits [N,4]
__device__ float g_edst[NN * NH];            // per-node dst logits [N,4]
__device__ int   g_deg[NN];
__device__ int   g_off[NN + 1];
__device__ int   g_part[SCAN_NB];            // per-block partial sums
__device__ int   g_partx[SCAN_NB];           // exclusive-scanned partials
__device__ int   g_pos[EE];                  // per-edge slot within its dst bucket
__device__ int   g_edge_src[EE];             // src ids grouped by dst (CSR)
__device__ int   g_is64;

// ---------------- f32x2 helpers (Blackwell packed fp32 — PTX only) ----------------
__device__ __forceinline__ unsigned long long pk2(float s) {
    unsigned long long d;
    asm("mov.b64 %0, {%1, %1};" : "=l"(d) : "f"(s));
    return d;
}
__device__ __forceinline__ void fma2(unsigned long long& c, unsigned long long a,
                                     unsigned long long b) {
    asm("fma.rn.f32x2 %0, %1, %2, %0;" : "+l"(c) : "l"(a), "l"(b));
}
__device__ __forceinline__ float2 up2(unsigned long long v) {
    float2 r;
    asm("mov.b64 {%0, %1}, %2;" : "=f"(r.x), "=f"(r.y) : "l"(v));
    return r;
}

// ---------------- helpers ----------------
__device__ __forceinline__ int edge_idx(const void* p, int i, int is64) {
    return is64 ? (int)((const long long*)p)[i] : ((const int*)p)[i];
}

// ---------------- init + dtype detect (fused) ----------------
__global__ void k_init(const void* src) {
    int i = blockIdx.x * blockDim.x + threadIdx.x;
    if (i < NN) g_deg[i] = 0;
    if (blockIdx.x == 0 && threadIdx.x < 32) {
        const unsigned* p = (const unsigned*)src;
        int lane = threadIdx.x;
        unsigned hi = p[2 * lane + 1] | p[2 * (lane + 32) + 1];
        unsigned b = __ballot_sync(0xffffffffu, hi == 0u);
        if (lane == 0) g_is64 = (b == 0xffffffffu) ? 1 : 0;
    }
}

// ---------------- GEMM + fused logits ----------------
// h = feat @ fc_w.T  (N x 128 @ 128 x 128), then e_src/e_dst per row.
// block = 256 threads, 64 rows x 128 cols. Packed fma.rn.f32x2 mainloop.
#define KC 32
__global__ void __launch_bounds__(256) k_gemm(const float* __restrict__ feat,
                                              const float* __restrict__ fc_w,
                                              const float* __restrict__ attn_src,
                                              const float* __restrict__ attn_dst) {
    __shared__ float wT[KC][132];
    __shared__ float fT[KC][68];
    int tid = threadIdx.x;
    int tx = tid & 31;
    int ty = tid >> 5;
    int rbase = blockIdx.x * 64;

    unsigned long long A[16];
#pragma unroll
    for (int r = 0; r < 16; r++) A[r] = 0ull;

    for (int k0 = 0; k0 < DIM; k0 += KC) {
        __syncthreads();
#pragma unroll
        for (int q = 0; q < 4; q++) {
            int id = tid + q * 256;
            int c  = id >> 3;
            int ks = (id & 7) * 4;
            float4 v = *(const float4*)&fc_w[c * DIM + k0 + ks];
            wT[ks + 0][c] = v.x; wT[ks + 1][c] = v.y;
            wT[ks + 2][c] = v.z; wT[ks + 3][c] = v.w;
        }
#pragma unroll
        for (int q = 0; q < 2; q++) {
            int id = tid + q * 256;
            int r  = id >> 3;
            int ks = (id & 7) * 4;
            int gr = rbase + r;
            float4 v = make_float4(0.f, 0.f, 0.f, 0.f);
            if (gr < NN) v = *(const float4*)&feat[(size_t)gr * DIM + k0 + ks];
            fT[ks + 0][r] = v.x; fT[ks + 1][r] = v.y;
            fT[ks + 2][r] = v.z; fT[ks + 3][r] = v.w;
        }
        __syncthreads();
#pragma unroll
        for (int kk = 0; kk < KC; kk++) {
            ulonglong2 w2 = *(const ulonglong2*)&wT[kk][tx * 4];
            float4 fa = *(const float4*)&fT[kk][ty * 8];
            float4 fb = *(const float4*)&fT[kk][ty * 8 + 4];
#define STEP(r, S) { unsigned long long b = pk2(S); \
                     fma2(A[2*(r)], w2.x, b); fma2(A[2*(r)+1], w2.y, b); }
            STEP(0, fa.x) STEP(1, fa.y) STEP(2, fa.z) STEP(3, fa.w)
            STEP(4, fb.x) STEP(5, fb.y) STEP(6, fb.z) STEP(7, fb.w)
#undef STEP
        }
    }

    float4 as4 = *(const float4*)&attn_src[tx * 4];
    float4 ad4 = *(const float4*)&attn_dst[tx * 4];
    int head = tx >> 3;

#pragma unroll
    for (int r = 0; r < 8; r++) {
        int gr = rbase + ty * 8 + r;
        float2 p0 = up2(A[2 * r]);
        float2 p1 = up2(A[2 * r + 1]);
        if (gr < NN) {
            __half2 ha = __floats2half2_rn(p0.x, p0.y);
            __half2 hb = __floats2half2_rn(p1.x, p1.y);
            uint2 u;
            u.x = *(const unsigned*)&ha;
            u.y = *(const unsigned*)&hb;
            g_hh[(size_t)gr * 32 + tx] = u;
        }
        float ps = p0.x * as4.x + p0.y * as4.y + p1.x * as4.z + p1.y * as4.w;
        float pd = p0.x * ad4.x + p0.y * ad4.y + p1.x * ad4.z + p1.y * ad4.w;
#pragma unroll
        for (int o = 1; o < 8; o <<= 1) {
            ps += __shfl_xor_sync(0xffffffffu, ps, o);
            pd += __shfl_xor_sync(0xffffffffu, pd, o);
        }
        if (gr < NN && (tx & 7) == 0) {
            g_esrc[gr * NH + head] = ps;
            g_edst[gr * NH + head] = pd;
        }
    }
}

// ---------------- CSR build ----------------
// histogram + record each edge's slot within its dst bucket
__global__ void k_hist(const void* __restrict__ dst) {
    int i = blockIdx.x * blockDim.x + threadIdx.x;
    if (i >= EE) return;
    int d = edge_idx(dst, i, g_is64);
    g_pos[i] = atomicAdd(&g_deg[d], 1);
}

// stage 1: per-block sums of g_deg
__global__ void __launch_bounds__(SCAN_B) k_scan1() {
    __shared__ int sm[SCAN_B];
    int t = threadIdx.x;
    int i = blockIdx.x * SCAN_B + t;
    sm[t] = (i < NN) ? g_deg[i] : 0;
    __syncthreads();
#pragma unroll
    for (int off = SCAN_B / 2; off > 0; off >>= 1) {
        if (t < off) sm[t] += sm[t + off];
        __syncthreads();
    }
    if (t == 0) g_part[blockIdx.x] = sm[0];
}

// stage 2: exclusive scan of SCAN_NB partials (one block)
__global__ void __launch_bounds__(256) k_scan2() {
    __shared__ int sm[256];
    int t = threadIdx.x;
    int v = (t < SCAN_NB) ? g_part[t] : 0;
    sm[t] = v;
    __syncthreads();
#pragma unroll
    for (int off = 1; off < 256; off <<= 1) {
        int x = (t >= off) ? sm[t - off] : 0;
        __syncthreads();
        sm[t] += x;
        __syncthreads();
    }
    if (t < SCAN_NB) g_partx[t] = sm[t] - v;   // exclusive
    if (t == 255) g_off[NN] = sm[255];          // total
}

// stage 3: per-block local scan + global offset -> g_off
__global__ void __launch_bounds__(SCAN_B) k_scan3() {
    __shared__ int sm[SCAN_B];
    int t = threadIdx.x;
    int i = blockIdx.x * SCAN_B + t;
    int v = (i < NN) ? g_deg[i] : 0;
    sm[t] = v;
    __syncthreads();
#pragma unroll
    for (int off = 1; off < SCAN_B; off <<= 1) {
        int x = (t >= off) ? sm[t - off] : 0;
        __syncthreads();
        sm[t] += x;
        __syncthreads();
    }
    if (i < NN) g_off[i] = g_partx[blockIdx.x] + sm[t] - v;   // exclusive
}

// scatter: no atomics — slot was recorded during hist
__global__ void k_scatter(const void* __restrict__ src, const void* __restrict__ dst) {
    int i = blockIdx.x * blockDim.x + threadIdx.x;
    if (i >= EE) return;
    int is64 = g_is64;
    int d = edge_idx(dst, i, is64);
    int s = edge_idx(src, i, is64);
    g_edge_src[g_off[d] + g_pos[i]] = s;
}

// ---------------- softmax + aggregation: warp per dst node, SINGLE pass ----------------
// acc = sum_e w_e * h[src_e]; norm = 1/sum_e w_e applied at the end.
// Every lane accumulates the (warp-uniform within head group) w-sum itself,
// so no shuffle reduce and no separate pass are needed.
__global__ void __launch_bounds__(256) k_agg(const float* __restrict__ feat,
                                             float* __restrict__ out) {
    int n = (blockIdx.x * blockDim.x + threadIdx.x) >> 5;
    int lane = threadIdx.x & 31;
    if (n >= NN) return;
    int beg = g_off[n], end = g_off[n + 1];
    float4 f4 = *(const float4*)&feat[(size_t)n * DIM + lane * 4];
    if (beg == end) {                 // no incoming edges: out = feat (residual)
        *(float4*)&out[(size_t)n * DIM + lane * 4] = f4;
        return;
    }
    int head = lane >> 3;             // this lane's 4 dims belong to one head
    float edh = g_edst[n * NH + head];

    const uint2* hh = g_hh;
    float ssum = 0.f;
    float4 acc = make_float4(0.f, 0.f, 0.f, 0.f);

    int i = beg;
    for (; i + 4 <= end; i += 4) {
        int s0 = g_edge_src[i];
        int s1 = g_edge_src[i + 1];
        int s2 = g_edge_src[i + 2];
        int s3 = g_edge_src[i + 3];
        float e0 = g_esrc[s0 * NH + head] + edh;
        float e1 = g_esrc[s1 * NH + head] + edh;
        float e2 = g_esrc[s2 * NH + head] + edh;
        float e3 = g_esrc[s3 * NH + head] + edh;
        uint2 u0 = hh[(size_t)s0 * 32 + lane];
        uint2 u1 = hh[(size_t)s1 * 32 + lane];
        uint2 u2 = hh[(size_t)s2 * 32 + lane];
        uint2 u3 = hh[(size_t)s3 * 32 + lane];
        e0 = e0 > 0.f ? e0 : 0.2f * e0;
        e1 = e1 > 0.f ? e1 : 0.2f * e1;
        e2 = e2 > 0.f ? e2 : 0.2f * e2;
        e3 = e3 > 0.f ? e3 : 0.2f * e3;
        float w0 = __expf(e0);
        float w1 = __expf(e1);
        float w2 = __expf(e2);
        float w3 = __expf(e3);
        ssum += (w0 + w1) + (w2 + w3);
        float2 a0 = __half22float2(*(const __half2*)&u0.x);
        float2 b0 = __half22float2(*(const __half2*)&u0.y);
        float2 a1 = __half22float2(*(const __half2*)&u1.x);
        float2 b1 = __half22float2(*(const __half2*)&u1.y);
        float2 a2 = __half22float2(*(const __half2*)&u2.x);
        float2 b2 = __half22float2(*(const __half2*)&u2.y);
        float2 a3 = __half22float2(*(const __half2*)&u3.x);
        float2 b3 = __half22float2(*(const __half2*)&u3.y);
        acc.x += w0 * a0.x; acc.y += w0 * a0.y;
        acc.z += w0 * b0.x; acc.w += w0 * b0.y;
        acc.x += w1 * a1.x; acc.y += w1 * a1.y;
        acc.z += w1 * b1.x; acc.w += w1 * b1.y;
        acc.x += w2 * a2.x; acc.y += w2 * a2.y;
        acc.z += w2 * b2.x; acc.w += w2 * b2.y;
        acc.x += w3 * a3.x; acc.y += w3 * a3.y;
        acc.z += w3 * b3.x; acc.w += w3 * b3.y;
    }
    for (; i < end; i++) {
        int s = g_edge_src[i];
        float e = g_esrc[s * NH + head] + edh;
        uint2 u = hh[(size_t)s * 32 + lane];
        e = e > 0.f ? e : 0.2f * e;
        float w = __expf(e);
        ssum += w;
        float2 a = __half22float2(*(const __half2*)&u.x);
        float2 b = __half22float2(*(const __half2*)&u.y);
        acc.x += w * a.x; acc.y += w * a.y;
        acc.z += w * b.x; acc.w += w * b.y;
    }
    float inv = 1.0f / ssum;          // ssum > 0 guaranteed (deg >= 1, exp > 0)
    float4 o4;
    o4.x = acc.x * inv + f4.x;
    o4.y = acc.y * inv + f4.y;
    o4.z = acc.z * inv + f4.z;
    o4.w = acc.w * inv + f4.w;
    *(float4*)&out[(size_t)n * DIM + lane * 4] = o4;
}

// ---------------- launch ----------------
extern "C" void kernel_launch(void* const* d_in, const int* in_sizes, int n_in,
                              void* d_out, int out_size) {
    const float* feat     = (const float*)d_in[0];
    const float* fc_w     = (const float*)d_in[1];
    const float* attn_src = (const float*)d_in[2];
    const float* attn_dst = (const float*)d_in[3];
    const void*  src      = d_in[4];
    const void*  dst      = d_in[5];
    float* out = (float*)d_out;

    static cudaStream_t s2 = nullptr;
    static cudaEvent_t evA = nullptr, evB = nullptr;
    if (!s2) {
        cudaStreamCreate(&s2);
        cudaEventCreateWithFlags(&evA, cudaEventDisableTiming);
        cudaEventCreateWithFlags(&evB, cudaEventDisableTiming);
    }

    // fork: CSR build chain on s2 (depends only on src/dst), GEMM on main stream
    cudaEventRecord(evA, 0);
    cudaStreamWaitEvent(s2, evA, 0);

    k_init<<<(NN + 255) / 256, 256, 0, s2>>>(src);
    k_hist<<<(EE + 255) / 256, 256, 0, s2>>>(dst);
    k_scan1<<<SCAN_NB, SCAN_B, 0, s2>>>();
    k_scan2<<<1, 256, 0, s2>>>();
    k_scan3<<<SCAN_NB, SCAN_B, 0, s2>>>();
    k_scatter<<<(EE + 255) / 256, 256, 0, s2>>>(src, dst);
    cudaEventRecord(evB, s2);

    k_gemm<<<(NN + 63) / 64, 256>>>(feat, fc_w, attn_src, attn_dst);

    // join, then aggregate
    cudaStreamWaitEvent(0, evB, 0);
    k_agg<<<(NN + 7) / 8, 256>>>(feat, out);
}

// round 11
// speedup vs baseline: 2.0397x; 1.3500x over previous
#include <cuda_runtime.h>
#include <cuda_bf16.h>
#include <cuda_fp16.h>

#define NN 100000
#define EE 1600000
#define DIM 128
#define NH 4
#define HD 32

#define SCAN_B 512
#define SCAN_NB ((NN + SCAN_B - 1) / SCAN_B)   // 196

// ---------------- device scratch (static — no allocation allowed) ----------------
__device__ uint2 g_hh[(size_t)NN * 32];      // projected features, fp16 [N,128]
__device__ float g_esrc[NN * NH];            // per-node src logits [N,4]
__device__ float g_edst[NN * NH];            // per-node dst logits [N,4]
__device__ int   g_deg[NN];
__device__ int   g_off[NN + 1];
__device__ int   g_part[SCAN_NB];            // per-block partial sums
__device__ int   g_partx[SCAN_NB];           // exclusive-scanned partials
__device__ int   g_pos[EE];                  // per-edge slot within its dst bucket
__device__ int   g_edge_src[EE];             // src ids grouped by dst (CSR)
__device__ int   g_is64;

// ---------------- helpers ----------------
__device__ __forceinline__ int edge_idx(const void* p, int i, int is64) {
    return is64 ? (int)((const long long*)p)[i] : ((const int*)p)[i];
}
__device__ __forceinline__ unsigned pkh2(float a, float b) {
    __half2 h = __floats2half2_rn(a, b);
    return *(unsigned*)&h;
}

// ---------------- init + dtype detect (fused) ----------------
__global__ void k_init(const void* src) {
    int i = blockIdx.x * blockDim.x + threadIdx.x;
    if (i < NN) g_deg[i] = 0;
    if (blockIdx.x == 0 && threadIdx.x < 32) {
        const unsigned* p = (const unsigned*)src;
        int lane = threadIdx.x;
        unsigned hi = p[2 * lane + 1] | p[2 * (lane + 32) + 1];
        unsigned b = __ballot_sync(0xffffffffu, hi == 0u);
        if (lane == 0) g_is64 = (b == 0xffffffffu) ? 1 : 0;
    }
}

// ---------------- GEMM via HMMA (mma.sync m16n8k16, fp16 in / fp32 accum) ----------------
// h = feat @ fc_w.T. Block: 128 rows x 128 cols x K=128.
// fc_w staged in smem as fp16 [n][k] padded; A-fragments loaded straight from gmem.
// Warp w computes rows [w*16, w*16+16) x all 128 cols -> fused logits stay in-warp.
#define SBK 136                       // padded k-extent (halves): row stride 272B
__global__ void __launch_bounds__(256) k_gemm(const float* __restrict__ feat,
                                              const float* __restrict__ fc_w,
                                              const float* __restrict__ attn_src,
                                              const float* __restrict__ attn_dst) {
    __shared__ __half sB[128][SBK];
    __shared__ float s_as[DIM], s_ad[DIM];
    int tid = threadIdx.x;
    int lane = tid & 31;
    int wm = tid >> 5;                // warp id 0..7 -> row strip
    int g = lane >> 2;                // 0..7
    int tig = lane & 3;               // 0..3
    int rbase = blockIdx.x * 128;

    // stage fc_w -> sB (fp16): 128 rows x 128 cols = 2048 ids x 8 floats
#pragma unroll
    for (int q = 0; q < 8; q++) {
        int id = tid + q * 256;       // 0..2047
        int n = id >> 4;              // 0..127
        int c = (id & 15) * 8;        // 0..120 step 8
        float4 v0 = *(const float4*)&fc_w[n * DIM + c];
        float4 v1 = *(const float4*)&fc_w[n * DIM + c + 4];
        unsigned* d = (unsigned*)&sB[n][c];
        d[0] = pkh2(v0.x, v0.y); d[1] = pkh2(v0.z, v0.w);
        d[2] = pkh2(v1.x, v1.y); d[3] = pkh2(v1.z, v1.w);
    }
    if (tid < DIM) { s_as[tid] = attn_src[tid]; s_ad[tid] = attn_dst[tid]; }
    __syncthreads();

    int r0 = rbase + wm * 16 + g;
    int r1 = r0 + 8;
    int ra = r0 < NN ? r0 : NN - 1;   // clamped addresses for loads
    int rb = r1 < NN ? r1 : NN - 1;
    const float* pa = feat + (size_t)ra * DIM;
    const float* pb = feat + (size_t)rb * DIM;

    float c0[16], c1[16], c2[16], c3[16];
#pragma unroll
    for (int ni = 0; ni < 16; ni++) { c0[ni] = 0.f; c1[ni] = 0.f; c2[ni] = 0.f; c3[ni] = 0.f; }

    unsigned A[2][4];
    {   // preload k-step 0
        int kk = 2 * tig;
        float2 v0 = *(const float2*)&pa[kk];
        float2 v1 = *(const float2*)&pb[kk];
        float2 v2 = *(const float2*)&pa[kk + 8];
        float2 v3 = *(const float2*)&pb[kk + 8];
        A[0][0] = pkh2(v0.x, v0.y); A[0][1] = pkh2(v1.x, v1.y);
        A[0][2] = pkh2(v2.x, v2.y); A[0][3] = pkh2(v3.x, v3.y);
    }

#pragma unroll
    for (int k = 0; k < 8; k++) {
        int cur = k & 1, nxt = cur ^ 1;
        if (k < 7) {
            int kk = (k + 1) * 16 + 2 * tig;
            float2 v0 = *(const float2*)&pa[kk];
            float2 v1 = *(const float2*)&pb[kk];
            float2 v2 = *(const float2*)&pa[kk + 8];
            float2 v3 = *(const float2*)&pb[kk + 8];
            A[nxt][0] = pkh2(v0.x, v0.y); A[nxt][1] = pkh2(v1.x, v1.y);
            A[nxt][2] = pkh2(v2.x, v2.y); A[nxt][3] = pkh2(v3.x, v3.y);
        }
        int kb = k * 16 + 2 * tig;
#pragma unroll
        for (int ni = 0; ni < 16; ni++) {
            unsigned b0 = *(const unsigned*)&sB[ni * 8 + g][kb];
            unsigned b1 = *(const unsigned*)&sB[ni * 8 + g][kb + 8];
            asm("mma.sync.aligned.m16n8k16.row.col.f32.f16.f16.f32 "
                "{%0,%1,%2,%3}, {%4,%5,%6,%7}, {%8,%9}, {%0,%1,%2,%3};"
                : "+f"(c0[ni]), "+f"(c1[ni]), "+f"(c2[ni]), "+f"(c3[ni])
                : "r"(A[cur][0]), "r"(A[cur][1]), "r"(A[cur][2]), "r"(A[cur][3]),
                  "r"(b0), "r"(b1));
        }
    }

    // ---- epilogue: store fp16 h + fused per-head logits ----
    unsigned* hu = (unsigned*)g_hh;   // [node][64] half2 view
    float ps0[NH] = {0, 0, 0, 0}, pd0[NH] = {0, 0, 0, 0};
    float ps1[NH] = {0, 0, 0, 0}, pd1[NH] = {0, 0, 0, 0};
#pragma unroll
    for (int ni = 0; ni < 16; ni++) {
        int n0 = ni * 8 + 2 * tig;
        int h = ni >> 2;
        float asx = s_as[n0], asy = s_as[n0 + 1];
        float adx = s_ad[n0], ady = s_ad[n0 + 1];
        ps0[h] += c0[ni] * asx + c1[ni] * asy;
        pd0[h] += c0[ni] * adx + c1[ni] * ady;
        ps1[h] += c2[ni] * asx + c3[ni] * asy;
        pd1[h] += c2[ni] * adx + c3[ni] * ady;
        if (r0 < NN) hu[(size_t)r0 * 64 + ni * 4 + tig] = pkh2(c0[ni], c1[ni]);
        if (r1 < NN) hu[(size_t)r1 * 64 + ni * 4 + tig] = pkh2(c2[ni], c3[ni]);
    }
#pragma unroll
    for (int o = 1; o < 4; o <<= 1) {
#pragma unroll
        for (int h = 0; h < NH; h++) {
            ps0[h] += __shfl_xor_sync(0xffffffffu, ps0[h], o);
            pd0[h] += __shfl_xor_sync(0xffffffffu, pd0[h], o);
            ps1[h] += __shfl_xor_sync(0xffffffffu, ps1[h], o);
            pd1[h] += __shfl_xor_sync(0xffffffffu, pd1[h], o);
        }
    }
    if (tig == 0) {
#pragma unroll
        for (int h = 0; h < NH; h++) {
            if (r0 < NN) { g_esrc[r0 * NH + h] = ps0[h]; g_edst[r0 * NH + h] = pd0[h]; }
            if (r1 < NN) { g_esrc[r1 * NH + h] = ps1[h]; g_edst[r1 * NH + h] = pd1[h]; }
        }
    }
}

// ---------------- CSR build ----------------
// histogram + record each edge's slot within its dst bucket
__global__ void k_hist(const void* __restrict__ dst) {
    int i = blockIdx.x * blockDim.x + threadIdx.x;
    if (i >= EE) return;
    int d = edge_idx(dst, i, g_is64);
    g_pos[i] = atomicAdd(&g_deg[d], 1);
}

// stage 1: per-block sums of g_deg
__global__ void __launch_bounds__(SCAN_B) k_scan1() {
    __shared__ int sm[SCAN_B];
    int t = threadIdx.x;
    int i = blockIdx.x * SCAN_B + t;
    sm[t] = (i < NN) ? g_deg[i] : 0;
    __syncthreads();
#pragma unroll
    for (int off = SCAN_B / 2; off > 0; off >>= 1) {
        if (t < off) sm[t] += sm[t + off];
        __syncthreads();
    }
    if (t == 0) g_part[blockIdx.x] = sm[0];
}

// stage 2: exclusive scan of SCAN_NB partials (one block)
__global__ void __launch_bounds__(256) k_scan2() {
    __shared__ int sm[256];
    int t = threadIdx.x;
    int v = (t < SCAN_NB) ? g_part[t] : 0;
    sm[t] = v;
    __syncthreads();
#pragma unroll
    for (int off = 1; off < 256; off <<= 1) {
        int x = (t >= off) ? sm[t - off] : 0;
        __syncthreads();
        sm[t] += x;
        __syncthreads();
    }
    if (t < SCAN_NB) g_partx[t] = sm[t] - v;   // exclusive
    if (t == 255) g_off[NN] = sm[255];          // total
}

// stage 3: per-block local scan + global offset -> g_off
__global__ void __launch_bounds__(SCAN_B) k_scan3() {
    __shared__ int sm[SCAN_B];
    int t = threadIdx.x;
    int i = blockIdx.x * SCAN_B + t;
    int v = (i < NN) ? g_deg[i] : 0;
    sm[t] = v;
    __syncthreads();
#pragma unroll
    for (int off = 1; off < SCAN_B; off <<= 1) {
        int x = (t >= off) ? sm[t - off] : 0;
        __syncthreads();
        sm[t] += x;
        __syncthreads();
    }
    if (i < NN) g_off[i] = g_partx[blockIdx.x] + sm[t] - v;   // exclusive
}

// scatter: no atomics — slot was recorded during hist
__global__ void k_scatter(const void* __restrict__ src, const void* __restrict__ dst) {
    int i = blockIdx.x * blockDim.x + threadIdx.x;
    if (i >= EE) return;
    int is64 = g_is64;
    int d = edge_idx(dst, i, is64);
    int s = edge_idx(src, i, is64);
    g_edge_src[g_off[d] + g_pos[i]] = s;
}

// ---------------- softmax + aggregation: warp per dst node, single pass ----------------
__global__ void __launch_bounds__(256) k_agg(const float* __restrict__ feat,
                                             float* __restrict__ out) {
    int n = (blockIdx.x * blockDim.x + threadIdx.x) >> 5;
    int lane = threadIdx.x & 31;
    if (n >= NN) return;
    int beg = g_off[n], end = g_off[n + 1];
    float4 f4 = *(const float4*)&feat[(size_t)n * DIM + lane * 4];
    if (beg == end) {                 // no incoming edges: out = feat (residual)
        *(float4*)&out[(size_t)n * DIM + lane * 4] = f4;
        return;
    }
    int head = lane >> 3;             // this lane's 4 dims belong to one head
    float edh = g_edst[n * NH + head];

    const uint2* hh = g_hh;
    float ssum = 0.f;
    float4 acc = make_float4(0.f, 0.f, 0.f, 0.f);

    int i = beg;
    for (; i + 4 <= end; i += 4) {
        int s0 = g_edge_src[i];
        int s1 = g_edge_src[i + 1];
        int s2 = g_edge_src[i + 2];
        int s3 = g_edge_src[i + 3];
        float e0 = g_esrc[s0 * NH + head] + edh;
        float e1 = g_esrc[s1 * NH + head] + edh;
        float e2 = g_esrc[s2 * NH + head] + edh;
        float e3 = g_esrc[s3 * NH + head] + edh;
        uint2 u0 = hh[(size_t)s0 * 32 + lane];
        uint2 u1 = hh[(size_t)s1 * 32 + lane];
        uint2 u2 = hh[(size_t)s2 * 32 + lane];
        uint2 u3 = hh[(size_t)s3 * 32 + lane];
        e0 = e0 > 0.f ? e0 : 0.2f * e0;
        e1 = e1 > 0.f ? e1 : 0.2f * e1;
        e2 = e2 > 0.f ? e2 : 0.2f * e2;
        e3 = e3 > 0.f ? e3 : 0.2f * e3;
        float w0 = __expf(e0);
        float w1 = __expf(e1);
        float w2 = __expf(e2);
        float w3 = __expf(e3);
        ssum += (w0 + w1) + (w2 + w3);
        float2 a0 = __half22float2(*(const __half2*)&u0.x);
        float2 b0 = __half22float2(*(const __half2*)&u0.y);
        float2 a1 = __half22float2(*(const __half2*)&u1.x);
        float2 b1 = __half22float2(*(const __half2*)&u1.y);
        float2 a2 = __half22float2(*(const __half2*)&u2.x);
        float2 b2 = __half22float2(*(const __half2*)&u2.y);
        float2 a3 = __half22float2(*(const __half2*)&u3.x);
        float2 b3 = __half22float2(*(const __half2*)&u3.y);
        acc.x += w0 * a0.x; acc.y += w0 * a0.y;
        acc.z += w0 * b0.x; acc.w += w0 * b0.y;
        acc.x += w1 * a1.x; acc.y += w1 * a1.y;
        acc.z += w1 * b1.x; acc.w += w1 * b1.y;
        acc.x += w2 * a2.x; acc.y += w2 * a2.y;
        acc.z += w2 * b2.x; acc.w += w2 * b2.y;
        acc.x += w3 * a3.x; acc.y += w3 * a3.y;
        acc.z += w3 * b3.x; acc.w += w3 * b3.y;
    }
    for (; i < end; i++) {
        int s = g_edge_src[i];
        float e = g_esrc[s * NH + head] + edh;
        uint2 u = hh[(size_t)s * 32 + lane];
        e = e > 0.f ? e : 0.2f * e;
        float w = __expf(e);
        ssum += w;
        float2 a = __half22float2(*(const __half2*)&u.x);
        float2 b = __half22float2(*(const __half2*)&u.y);
        acc.x += w * a.x; acc.y += w * a.y;
        acc.z += w * b.x; acc.w += w * b.y;
    }
    float inv = 1.0f / ssum;          // ssum > 0 guaranteed (deg >= 1, exp > 0)
    float4 o4;
    o4.x = acc.x * inv + f4.x;
    o4.y = acc.y * inv + f4.y;
    o4.z = acc.z * inv + f4.z;
    o4.w = acc.w * inv + f4.w;
    *(float4*)&out[(size_t)n * DIM + lane * 4] = o4;
}

// ---------------- launch ----------------
extern "C" void kernel_launch(void* const* d_in, const int* in_sizes, int n_in,
                              void* d_out, int out_size) {
    const float* feat     = (const float*)d_in[0];
    const float* fc_w     = (const float*)d_in[1];
    const float* attn_src = (const float*)d_in[2];
    const float* attn_dst = (const float*)d_in[3];
    const void*  src      = d_in[4];
    const void*  dst      = d_in[5];
    float* out = (float*)d_out;

    static cudaStream_t s2 = nullptr;
    static cudaEvent_t evA = nullptr, evB = nullptr;
    if (!s2) {
        cudaStreamCreate(&s2);
        cudaEventCreateWithFlags(&evA, cudaEventDisableTiming);
        cudaEventCreateWithFlags(&evB, cudaEventDisableTiming);
    }

    // fork: CSR build chain on s2 (depends only on src/dst), GEMM on main stream
    cudaEventRecord(evA, 0);
    cudaStreamWaitEvent(s2, evA, 0);

    k_init<<<(NN + 255) / 256, 256, 0, s2>>>(src);
    k_hist<<<(EE + 255) / 256, 256, 0, s2>>>(dst);
    k_scan1<<<SCAN_NB, SCAN_B, 0, s2>>>();
    k_scan2<<<1, 256, 0, s2>>>();
    k_scan3<<<SCAN_NB, SCAN_B, 0, s2>>>();
    k_scatter<<<(EE + 255) / 256, 256, 0, s2>>>(src, dst);
    cudaEventRecord(evB, s2);

    k_gemm<<<(NN + 127) / 128, 256>>>(feat, fc_w, attn_src, attn_dst);

    // join, then aggregate
    cudaStreamWaitEvent(0, evB, 0);
    k_agg<<<(NN + 7) / 8, 256>>>(feat, out);
}